// round 15
// baseline (speedup 1.0000x reference)
#include <cuda_runtime.h>

#define N_NODES 100000
#define N_EDGES 3200000
#define TPB     256
#define NP_MAX  2   // max nodes per thread; valid for grid >= 196 blocks

// Per-node partial sums for hidden units 0,1. Zero-init at load; Phase C
// consumes AND resets, so every graph replay sees zeros on entry.
static __device__ float g_acc[2 * N_NODES];
// Grid barrier counters; self-resetting each run (replay-safe).
static __device__ unsigned g_bar1 = 0, g_bar2 = 0;

// ---------------------------------------------------------------------------
// Persistent fused kernel. Launched at EXACTLY the runtime-measured residency
// (host occupancy query), so the spin barrier cannot deadlock.
// ---------------------------------------------------------------------------
__global__ void __launch_bounds__(TPB, 4) fused_kernel(
        const float4* __restrict__ ea,
        const int*    __restrict__ col,
        const float*  __restrict__ x,
        const float*  __restrict__ W1,
        const float*  __restrict__ b1,
        const float*  __restrict__ W2,
        const float*  __restrict__ b2,
        float*        __restrict__ out) {
    const int tid  = threadIdx.x;
    const int wid  = tid >> 5;
    const int lane = tid & 31;
    const int c    = lane & 3;
    const int gtid = blockIdx.x * TPB + tid;
    const int totThreads = gridDim.x * TPB;

    // ---------- Phase A: x-only node work (hides under Phase B stalls) -------
    float pre0[NP_MAX], pre1[NP_MAX], zc[NP_MAX];
#pragma unroll
    for (int k = 0; k < NP_MAX; ++k) {
        const int n = gtid + k * totThreads;
        if (n >= N_NODES) break;
        float vi = x[3 * n + 0];
        float s1 = x[3 * n + 1];
        float s2 = x[3 * n + 2];

        const float LC1 = log2f(0.7660379f);
        const float LC2 = log2f(0.12117091f);
        const float LC3 = log2f(1.2125463f);
        const float LC4 = log2f(0.1562228f);

        float p1 = exp2f((s2 / 0.3038425f + s1) * LC1);
        float p2 = exp2f(s1 * LC2);
        float p3 = exp2f(vi * LC3);
        float n1 = (p1 + p2 / -0.7256157f) * p3 + 0.12262904f;

        float t  = s2 + (s1 + -3.283101f - vi / 0.79082423f) * 0.31992579f;
        float p4 = exp2f(t * LC4);
        float n1n2 = 0.7872602f - sqrtf(logf(p4 + 1.4462701f));

        out[3 * n + 0] = n1 + vi;
        out[3 * n + 1] = (n1n2 - n1) + s1;

        pre0[k] = fmaf(vi, __ldg(&W1[0]),
                  fmaf(s1, __ldg(&W1[2]),
                  fmaf(s2, __ldg(&W1[4]), __ldg(&b1[0]))));
        pre1[k] = fmaf(vi, __ldg(&W1[1]),
                  fmaf(s1, __ldg(&W1[3]),
                  fmaf(s2, __ldg(&W1[5]), __ldg(&b1[1]))));
        zc[k] = __ldg(&b2[2]) + s2;   // b2[2] + s2 folded
    }

    // ---------- Phase B: edge aggregation (R6 proven layout, grid-strided) ---
    float w0[4], w1[4];
#pragma unroll
    for (int k = 0; k < 4; ++k) {
        w0[k] = __ldg(&W1[(3 + 4 * c + k) * 2 + 0]);
        w1[k] = __ldg(&W1[(3 + 4 * c + k) * 2 + 1]);
    }

    const int warpsTotal = gridDim.x * (TPB / 32);
    for (int chunk = blockIdx.x * (TPB / 32) + wid; chunk < N_EDGES / 32;
         chunk += warpsTotal) {
        const int eBase = chunk * 32;
        const int myCol = __ldg(col + eBase + lane);   // coalesced
        const float4* base = ea + (size_t)eBase * 4;
#pragma unroll
        for (int i = 0; i < 4; ++i) {
            float4 v = __ldg(base + lane + 32 * i);    // coalesced: 4 lines/LDG
            float d0 = fmaf(v.x, w0[0], fmaf(v.y, w0[1], fmaf(v.z, w0[2], v.w * w0[3])));
            float d1 = fmaf(v.x, w1[0], fmaf(v.y, w1[1], fmaf(v.z, w1[2], v.w * w1[3])));
            d0 += __shfl_xor_sync(0xffffffffu, d0, 1);
            d0 += __shfl_xor_sync(0xffffffffu, d0, 2);
            d1 += __shfl_xor_sync(0xffffffffu, d1, 1);
            d1 += __shfl_xor_sync(0xffffffffu, d1, 2);
            int nn = __shfl_sync(0xffffffffu, myCol, (lane >> 2) + 8 * i);
            if (c == 0) {
                float* p = g_acc + 2 * nn;   // 8B-aligned
                asm volatile("red.global.add.v2.f32 [%0], {%1, %2};"
                             :: "l"(p), "f"(d0), "f"(d1) : "memory");
            }
        }
    }

    // ---------- Grid barrier (co-residency guaranteed by host launch) --------
    __syncthreads();
    __threadfence();                 // make our REDs device-visible
    if (tid == 0) {
        atomicAdd(&g_bar1, 1u);
        while (atomicAdd(&g_bar1, 0u) < gridDim.x) __nanosleep(128);
    }
    __syncthreads();
    __threadfence();                 // acquire: all blocks' REDs visible

    // ---------- Phase C: finish column 2 -------------------------------------
#pragma unroll
    for (int k = 0; k < NP_MAX; ++k) {
        const int n = gtid + k * totThreads;
        if (n >= N_NODES) break;
        float2* accp = (float2*)(g_acc + 2 * n);
        float2 acc = *accp;
        *accp = make_float2(0.0f, 0.0f);   // reset for next replay
        float h0 = fmaxf(acc.x + pre0[k], 0.0f);
        float h1 = fmaxf(acc.y + pre1[k], 0.0f);
        out[3 * n + 2] = fmaf(h0, __ldg(&W2[2]), fmaf(h1, __ldg(&W2[5]), zc[k]));
    }

    // ---------- Counter reset (last block through; replay-safe) --------------
    __syncthreads();
    __threadfence();
    if (tid == 0) {
        if (atomicAdd(&g_bar2, 1u) == gridDim.x - 1u) {
            g_bar1 = 0u;
            g_bar2 = 0u;
            __threadfence();
        }
    }
}

// ---------------------------------------------------------------------------
// Fallback path: the proven two-kernel R6 structure (46.46 us).
// ---------------------------------------------------------------------------
__global__ void __launch_bounds__(256) edge_kernel(
        const float4* __restrict__ ea,
        const int*    __restrict__ col,
        const float*  __restrict__ W1) {
    const int warp_id = (blockIdx.x * blockDim.x + threadIdx.x) >> 5;
    const int lane = threadIdx.x & 31;
    const int eBase = warp_id * 32;
    const int c = lane & 3;

    float w0[4], w1[4];
#pragma unroll
    for (int k = 0; k < 4; ++k) {
        w0[k] = __ldg(&W1[(3 + 4 * c + k) * 2 + 0]);
        w1[k] = __ldg(&W1[(3 + 4 * c + k) * 2 + 1]);
    }
    const int myCol = __ldg(col + eBase + lane);
    const float4* base = ea + (size_t)eBase * 4;
#pragma unroll
    for (int i = 0; i < 4; ++i) {
        float4 v = __ldg(base + lane + 32 * i);
        float d0 = fmaf(v.x, w0[0], fmaf(v.y, w0[1], fmaf(v.z, w0[2], v.w * w0[3])));
        float d1 = fmaf(v.x, w1[0], fmaf(v.y, w1[1], fmaf(v.z, w1[2], v.w * w1[3])));
        d0 += __shfl_xor_sync(0xffffffffu, d0, 1);
        d0 += __shfl_xor_sync(0xffffffffu, d0, 2);
        d1 += __shfl_xor_sync(0xffffffffu, d1, 1);
        d1 += __shfl_xor_sync(0xffffffffu, d1, 2);
        int n = __shfl_sync(0xffffffffu, myCol, (lane >> 2) + 8 * i);
        if (c == 0) {
            float* p = g_acc + 2 * n;
            asm volatile("red.global.add.v2.f32 [%0], {%1, %2};"
                         :: "l"(p), "f"(d0), "f"(d1) : "memory");
        }
    }
}

__global__ void __launch_bounds__(128) node_kernel(
        const float* __restrict__ x,
        const float* __restrict__ W1,
        const float* __restrict__ b1,
        const float* __restrict__ W2,
        const float* __restrict__ b2,
        float* __restrict__ out) {
    int n = blockIdx.x * blockDim.x + threadIdx.x;
    if (n >= N_NODES) return;

    float vi = x[3 * n + 0];
    float s1 = x[3 * n + 1];
    float s2 = x[3 * n + 2];

    float2* accp = (float2*)(g_acc + 2 * n);
    float2 acc = *accp;
    *accp = make_float2(0.0f, 0.0f);

    float h0 = acc.x + __ldg(&b1[0]);
    h0 = fmaf(vi, __ldg(&W1[0]), fmaf(s1, __ldg(&W1[2]), fmaf(s2, __ldg(&W1[4]), h0)));
    float h1 = acc.y + __ldg(&b1[1]);
    h1 = fmaf(vi, __ldg(&W1[1]), fmaf(s1, __ldg(&W1[3]), fmaf(s2, __ldg(&W1[5]), h1)));
    h0 = fmaxf(h0, 0.0f);
    h1 = fmaxf(h1, 0.0f);
    float o2 = fmaf(h0, __ldg(&W2[2]), fmaf(h1, __ldg(&W2[5]), __ldg(&b2[2])));

    const float LC1 = log2f(0.7660379f);
    const float LC2 = log2f(0.12117091f);
    const float LC3 = log2f(1.2125463f);
    const float LC4 = log2f(0.1562228f);

    float p1 = exp2f((s2 / 0.3038425f + s1) * LC1);
    float p2 = exp2f(s1 * LC2);
    float p3 = exp2f(vi * LC3);
    float n1 = (p1 + p2 / -0.7256157f) * p3 + 0.12262904f;

    float t = s2 + (s1 + -3.283101f - vi / 0.79082423f) * 0.31992579f;
    float p4 = exp2f(t * LC4);
    float n1n2 = 0.7872602f - sqrtf(logf(p4 + 1.4462701f));

    out[3 * n + 0] = n1 + vi;
    out[3 * n + 1] = (n1n2 - n1) + s1;
    out[3 * n + 2] = o2 + s2;
}

extern "C" void kernel_launch(void* const* d_in, const int* in_sizes, int n_in,
                              void* d_out, int out_size) {
    // metadata order: x, edge_attr, u, W1, b1, W2, b2, edge_index, batch
    const float*  x   = (const float*)d_in[0];
    const float4* ea  = (const float4*)d_in[1];
    const float*  W1  = (const float*)d_in[3];
    const float*  b1  = (const float*)d_in[4];
    const float*  W2  = (const float*)d_in[5];
    const float*  b2  = (const float*)d_in[6];
    const int*    ei  = (const int*)d_in[7];   // int32 (JAX x64 off)
    const int*    col = ei + N_EDGES;          // edge_index[1]
    float* out = (float*)d_out;

    // Runtime co-residency measurement (pure queries: capture-legal,
    // deterministic per device).
    int dev = 0, sms = 0, maxb = 0;
    cudaGetDevice(&dev);
    cudaDeviceGetAttribute(&sms, cudaDevAttrMultiProcessorCount, dev);
    cudaOccupancyMaxActiveBlocksPerMultiprocessor(&maxb, fused_kernel, TPB, 0);
    int grid = sms * maxb;

    if (grid >= 196) {   // NP_MAX=2 covers all nodes; barrier provably safe
        fused_kernel<<<grid, TPB>>>(ea, col, x, W1, b1, W2, b2, out);
    } else {
        edge_kernel<<<N_EDGES / 32 / 8, 256>>>(ea, col, W1);
        node_kernel<<<(N_NODES + 127) / 128, 128>>>(x, W1, b1, W2, b2, out);
    }
}

// round 16
// speedup vs baseline: 1.2495x; 1.2495x over previous
#include <cuda_runtime.h>

#define N_NODES 100000
#define N_EDGES 3200000

// Per-node partial sums for hidden units 0,1 (interleaved for v2 atomics).
// Zero-initialized at module load; node_kernel consumes AND resets, so every
// replay of the captured graph sees zeros on entry.
static __device__ float g_acc[2 * N_NODES];

// Warp-cooperative, fully coalesced edge aggregation (R6 layout: 32 edges/warp).
// Lane l loads float4 flat = 128w + l + 32i (coalesced), chunk c=l&3 of edge
// 32w + (l>>2) + 8i. Butterfly shuffles (xor 1,2) sum the 4 chunk-dots;
// lane 4j issues one red.global.add.v2.f32.
// __launch_bounds__(256, 8): cap 32 regs -> 2048 threads = 64 warps/SM.
// R15 profile showed this kernel is latency-bound (DRAM 49%, issue 22%,
// runtime ~ 1/resident-warps), so occupancy is the binding resource.
__global__ void __launch_bounds__(256, 8) edge_kernel(
        const float4* __restrict__ ea,
        const int*    __restrict__ col,
        const float*  __restrict__ W1) {
    const int warp_id = (blockIdx.x * blockDim.x + threadIdx.x) >> 5;
    const int lane = threadIdx.x & 31;
    const int eBase = warp_id * 32;
    const int c = lane & 3;

    // W1 is [19,2] row-major; edge-feature rows are 3..18. Chunk c -> rows 3+4c..6+4c.
    float w0[4], w1[4];
#pragma unroll
    for (int k = 0; k < 4; ++k) {
        w0[k] = __ldg(&W1[(3 + 4 * c + k) * 2 + 0]);
        w1[k] = __ldg(&W1[(3 + 4 * c + k) * 2 + 1]);
    }

    const int myCol = __ldg(col + eBase + lane);       // coalesced
    const float4* base = ea + (size_t)eBase * 4;

#pragma unroll
    for (int i = 0; i < 4; ++i) {
        float4 v = __ldg(base + lane + 32 * i);        // coalesced: 4 lines/LDG
        float d0 = fmaf(v.x, w0[0], fmaf(v.y, w0[1], fmaf(v.z, w0[2], v.w * w0[3])));
        float d1 = fmaf(v.x, w1[0], fmaf(v.y, w1[1], fmaf(v.z, w1[2], v.w * w1[3])));
        d0 += __shfl_xor_sync(0xffffffffu, d0, 1);
        d0 += __shfl_xor_sync(0xffffffffu, d0, 2);
        d1 += __shfl_xor_sync(0xffffffffu, d1, 1);
        d1 += __shfl_xor_sync(0xffffffffu, d1, 2);
        // lane 4j now holds the full dot of edge eBase + j + 8i
        int n = __shfl_sync(0xffffffffu, myCol, (lane >> 2) + 8 * i);
        if (c == 0) {
            float* p = g_acc + 2 * n;  // 8B-aligned
            asm volatile("red.global.add.v2.f32 [%0], {%1, %2};"
                         :: "l"(p), "f"(d0), "f"(d1) : "memory");
        }
    }
}

__global__ void __launch_bounds__(128) node_kernel(
        const float* __restrict__ x,
        const float* __restrict__ W1,
        const float* __restrict__ b1,
        const float* __restrict__ W2,
        const float* __restrict__ b2,
        float* __restrict__ out) {
    int n = blockIdx.x * blockDim.x + threadIdx.x;
    if (n >= N_NODES) return;

    float vi = x[3 * n + 0];
    float s1 = x[3 * n + 1];
    float s2 = x[3 * n + 2];

    // Consume and reset accumulator (keeps g_acc zeroed for the next replay).
    float2* accp = (float2*)(g_acc + 2 * n);
    float2 acc = *accp;
    *accp = make_float2(0.0f, 0.0f);

    float h0 = acc.x + __ldg(&b1[0]);
    h0 = fmaf(vi, __ldg(&W1[0]), fmaf(s1, __ldg(&W1[2]), fmaf(s2, __ldg(&W1[4]), h0)));
    float h1 = acc.y + __ldg(&b1[1]);
    h1 = fmaf(vi, __ldg(&W1[1]), fmaf(s1, __ldg(&W1[3]), fmaf(s2, __ldg(&W1[5]), h1)));
    h0 = fmaxf(h0, 0.0f);
    h1 = fmaxf(h1, 0.0f);
    float o2 = fmaf(h0, __ldg(&W2[2]), fmaf(h1, __ldg(&W2[5]), __ldg(&b2[2])));

    // closed-form overrides (x-only). powf(c,t) == exp2f(t*log2f(c)).
    const float LC1 = log2f(0.7660379f);
    const float LC2 = log2f(0.12117091f);
    const float LC3 = log2f(1.2125463f);
    const float LC4 = log2f(0.1562228f);

    float p1 = exp2f((s2 / 0.3038425f + s1) * LC1);
    float p2 = exp2f(s1 * LC2);
    float p3 = exp2f(vi * LC3);
    float n1 = (p1 + p2 / -0.7256157f) * p3 + 0.12262904f;

    float t = s2 + (s1 + -3.283101f - vi / 0.79082423f) * 0.31992579f;
    float p4 = exp2f(t * LC4);
    float n1n2 = 0.7872602f - sqrtf(logf(p4 + 1.4462701f));

    out[3 * n + 0] = n1 + vi;
    out[3 * n + 1] = (n1n2 - n1) + s1;
    out[3 * n + 2] = o2 + s2;
}

extern "C" void kernel_launch(void* const* d_in, const int* in_sizes, int n_in,
                              void* d_out, int out_size) {
    // metadata order: x, edge_attr, u, W1, b1, W2, b2, edge_index, batch
    const float*  x   = (const float*)d_in[0];
    const float4* ea  = (const float4*)d_in[1];
    const float*  W1  = (const float*)d_in[3];
    const float*  b1  = (const float*)d_in[4];
    const float*  W2  = (const float*)d_in[5];
    const float*  b2  = (const float*)d_in[6];
    const int*    ei  = (const int*)d_in[7];   // int32 (JAX x64 off)
    const int*    col = ei + N_EDGES;          // edge_index[1]
    float* out = (float*)d_out;

    // 100000 warps (32 edges each), 8 warps/block -> 12500 blocks, no tail.
    edge_kernel<<<N_EDGES / 32 / 8, 256>>>(ea, col, W1);
    node_kernel<<<(N_NODES + 127) / 128, 128>>>(x, W1, b1, W2, b2, out);
}